// round 8
// baseline (speedup 1.0000x reference)
#include <cuda_runtime.h>
#include <cuda_bf16.h>
#include <cuda_fp16.h>
#include <cstdint>
#include <cstddef>

#define BB 8
#define LL 2048
#define DD 1024

// ---------------- scratch (device globals; allocation-free) ----------------
__device__ float g_ks[BB * LL];
__device__ float g_e[BB * LL];
__device__ float g_zinv[BB * LL];
__device__ int g_is32;
__device__ unsigned char g_mask8[(size_t)BB * LL * LL];  // 0/1 bytes (zattn)
__device__ __half g_mf16[(size_t)BB * LL * LL];          // mask as fp16 0/1 (GEMM A)
__device__ __half g_ut[(size_t)BB * DD * LL];            // U^T fp16: [b][d][s]

// ---------------- helpers ----------------
static __device__ __forceinline__ uint32_t smem_u32(const void* p) {
    uint32_t a;
    asm("{ .reg .u64 t; cvta.to.shared.u64 t, %1; cvt.u32.u64 %0, t; }" : "=r"(a) : "l"(p));
    return a;
}

#define STS128V(a, r0, r1, r2, r3) \
    asm volatile("st.shared.v4.b32 [%0], {%1, %2, %3, %4};" :: "r"(a), "r"(r0), "r"(r1), "r"(r2), "r"(r3) : "memory")

#define CPASYNC16(dst, src) \
    asm volatile("cp.async.cg.shared.global [%0], [%1], 16;" :: "r"(dst), "l"(src) : "memory")
#define CPCOMMIT() asm volatile("cp.async.commit_group;" ::: "memory")
#define CPWAIT1() asm volatile("cp.async.wait_group 1;" ::: "memory")

static __device__ __forceinline__ void ldsm4(uint32_t* r, uint32_t addr) {
    asm volatile("ldmatrix.sync.aligned.m8n8.x4.shared.b16 {%0,%1,%2,%3}, [%4];"
                 : "=r"(r[0]), "=r"(r[1]), "=r"(r[2]), "=r"(r[3]) : "r"(addr));
}

static __device__ __forceinline__ void mma_f16(float* c, const uint32_t* a, const uint32_t* b) {
    asm volatile(
        "mma.sync.aligned.m16n8k16.row.col.f32.f16.f16.f32 "
        "{%0,%1,%2,%3}, {%4,%5,%6,%7}, {%8,%9}, {%0,%1,%2,%3};"
        : "+f"(c[0]), "+f"(c[1]), "+f"(c[2]), "+f"(c[3])
        : "r"(a[0]), "r"(a[1]), "r"(a[2]), "r"(a[3]), "r"(b[0]), "r"(b[1]));
}

// swizzled SMEM offset: tiles are 128 rows x 64 fp16 (128B rows, 8 x 16B chunks)
#define SA(row, chunk) ((uint32_t)((row) * 128 + ((((uint32_t)(chunk)) ^ ((uint32_t)(row) & 7u)) << 4)))

// 2 mask bytes -> fp16x2 (1.0 where NOT masked, 0.0 where masked)
static __device__ __forceinline__ uint32_t m2f16(uint32_t w) {
    uint32_t lo = (w & 0x000000FFu) ? 0u : 0x3C00u;
    uint32_t hi = (w & 0x0000FF00u) ? 0u : 0x3C00u;
    return lo | (hi << 16);
}

// ---------------- Pass 0a: detect mask dtype (int32 vs uint8) ----------------
__global__ void detect_kernel(const unsigned int* m) {
    __shared__ int s;
    if (threadIdx.x == 0) s = 0;
    __syncthreads();
    if (m[threadIdx.x] & 0xFFFFFF00u) atomicOr(&s, 1);
    __syncthreads();
    if (threadIdx.x == 0) g_is32 = s ? 0 : 1;
}

// ---------------- Pass 0b: repack mask to bytes + fp16 ----------------
__global__ __launch_bounds__(256) void repack_kernel(const void* maskp) {
    size_t base = ((size_t)blockIdx.x * 256 + threadIdx.x) * 16;
    unsigned char ob[16];
    if (g_is32) {
        const uint4* mi = (const uint4*)((const int*)maskp + base);
#pragma unroll
        for (int j = 0; j < 4; j++) {
            uint4 w = mi[j];
            ob[j * 4 + 0] = w.x ? 1 : 0;
            ob[j * 4 + 1] = w.y ? 1 : 0;
            ob[j * 4 + 2] = w.z ? 1 : 0;
            ob[j * 4 + 3] = w.w ? 1 : 0;
        }
    } else {
        *(uint4*)ob = *(const uint4*)((const unsigned char*)maskp + base);
    }
    *(uint4*)(g_mask8 + base) = *(uint4*)ob;
    // fp16 0/1
    uint32_t mf[8];
#pragma unroll
    for (int j = 0; j < 8; j++) {
        uint32_t lo = ob[2 * j] ? 0u : 0x3C00u;
        uint32_t hi = ob[2 * j + 1] ? 0u : 0x3C00u;
        mf[j] = lo | (hi << 16);
    }
    uint4* mfp = (uint4*)((unsigned char*)g_mf16 + base * 2);
    mfp[0] = make_uint4(mf[0], mf[1], mf[2], mf[3]);
    mfp[1] = make_uint4(mf[4], mf[5], mf[6], mf[7]);
}

// ---------------- Pass 1: k_s[b,s] = k . W2 + b2 ----------------
__global__ __launch_bounds__(256) void ks_kernel(const float* __restrict__ k,
                                                 const float* __restrict__ W2,
                                                 const float* __restrict__ b2) {
    int w = threadIdx.x >> 5, lane = threadIdx.x & 31;
    int r = blockIdx.x * 8 + w;
    const float4* kr = (const float4*)(k + (size_t)r * DD);
    const float4* w4 = (const float4*)W2;
    float s = 0.f;
#pragma unroll
    for (int i = 0; i < 8; i++) {
        float4 a = kr[lane + 32 * i];
        float4 b = w4[lane + 32 * i];
        s += a.x * b.x + a.y * b.y + a.z * b.z + a.w * b.w;
    }
#pragma unroll
    for (int o = 16; o; o >>= 1) s += __shfl_xor_sync(0xFFFFFFFFu, s, o);
    if (lane == 0) g_ks[r] = s + b2[0];
}

// ---------------- Pass 2: per-b max and e = exp(ks - max) ----------------
__global__ __launch_bounds__(256) void maxexp_kernel() {
    int b = blockIdx.x;
    __shared__ float red[256];
    float m = -1e30f;
    for (int i = threadIdx.x; i < LL; i += 256) m = fmaxf(m, g_ks[b * LL + i]);
    red[threadIdx.x] = m;
    __syncthreads();
    for (int s = 128; s; s >>= 1) {
        if (threadIdx.x < s) red[threadIdx.x] = fmaxf(red[threadIdx.x], red[threadIdx.x + s]);
        __syncthreads();
    }
    float M = red[0];
    for (int i = threadIdx.x; i < LL; i += 256) g_e[b * LL + i] = expf(g_ks[b * LL + i] - M);
}

// ---------------- Pass 3: U^T fp16 build (U = e * v, transposed to [b][d][s]) ----------------
__global__ __launch_bounds__(256) void ut_kernel(const float* __restrict__ v) {
    __shared__ float tile[32][33];
    int b = blockIdx.z;
    int s0 = blockIdx.y * 32, d0 = blockIdx.x * 32;
    int r = threadIdx.x >> 5, c = threadIdx.x & 31;
#pragma unroll
    for (int i = 0; i < 4; i++) {
        int sl = r + i * 8;
        tile[sl][c] = g_e[b * LL + s0 + sl] * v[((size_t)b * LL + s0 + sl) * DD + d0 + c];
    }
    __syncthreads();
#pragma unroll
    for (int i = 0; i < 4; i++) {
        int dl = r + i * 8;
        float u = tile[c][dl];
        g_ut[((size_t)b * DD + d0 + dl) * LL + s0 + c] = __float2half(u);
    }
}

// ---------------- Pass 4: Z[b,l], zinv, attn output ----------------
__global__ __launch_bounds__(256) void zattn_kernel(float* __restrict__ attn) {
    __shared__ __align__(16) float se[LL];
    int b = blockIdx.x >> 8;
    int l0 = (blockIdx.x & 255) * 8;
    for (int i = threadIdx.x; i < LL; i += 256) se[i] = g_e[b * LL + i];
    __syncthreads();
    int w = threadIdx.x >> 5, lane = threadIdx.x & 31;
    int l = l0 + w;
    const uint32_t* mrow = (const uint32_t*)(g_mask8 + ((size_t)b * LL + l) * LL);
    const float4* e4 = (const float4*)se;
    uint32_t mw[16];
    float z = 0.f;
#pragma unroll
    for (int i = 0; i < 16; i++) {
        uint32_t m = mrow[lane + 32 * i];
        mw[i] = m;
        float4 ev = e4[lane + 32 * i];
        if (!(m & 0x000000FFu)) z += ev.x;
        if (!(m & 0x0000FF00u)) z += ev.y;
        if (!(m & 0x00FF0000u)) z += ev.z;
        if (!(m & 0xFF000000u)) z += ev.w;
    }
#pragma unroll
    for (int o = 16; o; o >>= 1) z += __shfl_xor_sync(0xFFFFFFFFu, z, o);
    float zi = 1.f / z;
    if (lane == 0) g_zinv[b * LL + l] = zi;
    float4* arow = (float4*)(attn + ((size_t)b * LL + l) * LL);
#pragma unroll
    for (int i = 0; i < 16; i++) {
        uint32_t m = mw[i];
        float4 ev = e4[lane + 32 * i];
        float4 o4;
        o4.x = (m & 0x000000FFu) ? 0.f : ev.x * zi;
        o4.y = (m & 0x0000FF00u) ? 0.f : ev.y * zi;
        o4.z = (m & 0x00FF0000u) ? 0.f : ev.z * zi;
        o4.w = (m & 0xFF000000u) ? 0.f : ev.w * zi;
        arow[lane + 32 * i] = o4;
    }
}

// ================= Pass 5 (preferred): 3-stage all-cp.async fp16 GEMM, 96KB dyn SMEM =================
// CTA tile 128(l) x 128(d), K-chunk 64(s), stage st: [A 16KB | B 16KB].
// Loop: wait -> barrier -> prefetch(kt+2) -> compute(kt). One barrier per chunk.
__global__ __launch_bounds__(256, 2) void gemm_kernel96(float* __restrict__ out) {
    extern __shared__ __align__(128) unsigned char dsm[];
    uint32_t sb = smem_u32(dsm);
    int tid = threadIdx.x, wid = tid >> 5, lane = tid & 31;
    int b = blockIdx.z, l0 = blockIdx.y * 128, d0 = blockIdx.x * 128;
    int warpM = wid & 3, warpN = wid >> 2;

    float acc[2][8][4];
#pragma unroll
    for (int i = 0; i < 2; i++)
#pragma unroll
        for (int j = 0; j < 8; j++)
#pragma unroll
            for (int q = 0; q < 4; q++) acc[i][j][q] = 0.f;

    int sub = lane >> 3, l7 = lane & 7;
    int rA0 = warpM * 32 + (sub & 1) * 8 + l7;
    int chA = (sub >> 1);
    int rB0 = warpN * 64 + (sub >> 1) * 8 + l7;
    int chB = (sub & 1);

    int srow = tid >> 1;
    int sc4 = (tid & 1) * 4;
    const __half* mp = g_mf16 + ((size_t)(b * LL + l0 + srow)) * LL + sc4 * 8;
    const __half* up = g_ut + ((size_t)(b * DD + d0 + srow)) * LL + sc4 * 8;
    // per-thread swizzled staging offsets (4 consecutive chunks)
    uint32_t so[4];
#pragma unroll
    for (int j = 0; j < 4; j++) so[j] = SA(srow, sc4 + j);

    // ---- prologue: stages 0 and 1 ----
#pragma unroll
    for (int st = 0; st < 2; st++) {
        uint32_t ab = sb + (uint32_t)st * 32768u;
#pragma unroll
        for (int j = 0; j < 4; j++)
            CPASYNC16(ab + so[j], (const void*)(mp + st * 64 + j * 8));
#pragma unroll
        for (int j = 0; j < 4; j++)
            CPASYNC16(ab + 16384u + so[j], (const void*)(up + st * 64 + j * 8));
        CPCOMMIT();
    }

    int st = 0;  // kt % 3
    for (int kt = 0; kt < 32; ++kt) {
        CPWAIT1();       // stage kt landed (only kt+1 pending)
        __syncthreads(); // all warps done compute(kt-1); stage (kt+2)%3 free; stage kt visible

        // ---- prefetch stage kt+2 (overlaps compute below) ----
        if (kt < 30) {
            int s0n = (kt + 2) * 64;
            int stn = st + 2; if (stn >= 3) stn -= 3;
            uint32_t nb = sb + (uint32_t)stn * 32768u;
#pragma unroll
            for (int j = 0; j < 4; j++)
                CPASYNC16(nb + so[j], (const void*)(mp + s0n + j * 8));
#pragma unroll
            for (int j = 0; j < 4; j++)
                CPASYNC16(nb + 16384u + so[j], (const void*)(up + s0n + j * 8));
        }
        CPCOMMIT();  // one group per iteration (possibly empty in tail)

        // ---- compute chunk kt from stage st ----
        uint32_t abase = sb + (uint32_t)st * 32768u;
        uint32_t bbase = abase + 16384u;
#pragma unroll
        for (int ki = 0; ki < 4; ki++) {
            uint32_t af[2][4];
#pragma unroll
            for (int mi = 0; mi < 2; mi++)
                ldsm4(af[mi], abase + SA(rA0 + mi * 16, ki * 2 + chA));
#pragma unroll
            for (int p = 0; p < 4; p++) {
                uint32_t bf[4];
                ldsm4(bf, bbase + SA(rB0 + p * 16, ki * 2 + chB));
#pragma unroll
                for (int mi = 0; mi < 2; mi++) {
                    mma_f16(acc[mi][2 * p], af[mi], bf);
                    mma_f16(acc[mi][2 * p + 1], af[mi], bf + 2);
                }
            }
        }
        if (++st == 3) st = 0;
    }

    // epilogue
    int g = lane >> 2, tg = lane & 3;
#pragma unroll
    for (int mi = 0; mi < 2; mi++) {
#pragma unroll
        for (int h = 0; h < 2; h++) {
            int row = warpM * 32 + mi * 16 + h * 8 + g;
            float zi = g_zinv[b * LL + l0 + row];
            float* orow = out + ((size_t)(b * LL + l0 + row)) * DD + d0 + warpN * 64;
#pragma unroll
            for (int ni = 0; ni < 8; ni++) {
                float2 val;
                val.x = acc[mi][ni][h * 2] * zi;
                val.y = acc[mi][ni][h * 2 + 1] * zi;
                *(float2*)(orow + ni * 8 + tg * 2) = val;
            }
        }
    }
}

// ================= Pass 5 (fallback): 48KB static, 2-stage, all-cp.async =================
__global__ __launch_bounds__(256, 2) void gemm_kernel48(float* __restrict__ out) {
    __shared__ __align__(128) unsigned char smem[49152];  // A 16K + B双 2x16K
    uint32_t sb = smem_u32(smem);
    int tid = threadIdx.x, wid = tid >> 5, lane = tid & 31;
    int b = blockIdx.z, l0 = blockIdx.y * 128, d0 = blockIdx.x * 128;
    int warpM = wid & 3, warpN = wid >> 2;

    float acc[2][8][4];
#pragma unroll
    for (int i = 0; i < 2; i++)
#pragma unroll
        for (int j = 0; j < 8; j++)
#pragma unroll
            for (int q = 0; q < 4; q++) acc[i][j][q] = 0.f;

    int sub = lane >> 3, l7 = lane & 7;
    int rA0 = warpM * 32 + (sub & 1) * 8 + l7;
    int chA = (sub >> 1);
    int rB0 = warpN * 64 + (sub >> 1) * 8 + l7;
    int chB = (sub & 1);

    int srow = tid >> 1;
    int sc4 = (tid & 1) * 4;
    const __half* mp = g_mf16 + ((size_t)(b * LL + l0 + srow)) * LL + sc4 * 8;
    const __half* up = g_ut + ((size_t)(b * DD + d0 + srow)) * LL + sc4 * 8;
    uint32_t so[4];
#pragma unroll
    for (int j = 0; j < 4; j++) so[j] = SA(srow, sc4 + j);

    uint2 areg[4];
#pragma unroll
    for (int j = 0; j < 4; j++) areg[j] = *(const uint2*)((const unsigned char*)mp + 0 + j * 16);  // fp16 A regs direct
#pragma unroll
    for (int j = 0; j < 4; j++)
        CPASYNC16(sb + 16384u + so[j], (const void*)(up + 0 + j * 8));
    CPCOMMIT();
#pragma unroll
    for (int j = 0; j < 4; j++)
        CPASYNC16(sb + 32768u + so[j], (const void*)(up + 64 + j * 8));
    CPCOMMIT();
    // A(0) regs are actually 16B each chunk; stage via STS (areg holds halves pre-formatted fp16)
#pragma unroll
    for (int j = 0; j < 4; j++) {
        uint4 av = *(const uint4*)(mp + 0 + j * 8);
        STS128V(sb + so[j], av.x, av.y, av.z, av.w);
    }
    CPWAIT1();
    __syncthreads();

    for (int kt = 0; kt < 32; ++kt) {
        uint32_t bbase = sb + 16384u + (uint32_t)(kt & 1) * 16384u;
#pragma unroll
        for (int ki = 0; ki < 4; ki++) {
            uint32_t af[2][4];
#pragma unroll
            for (int mi = 0; mi < 2; mi++)
                ldsm4(af[mi], sb + SA(rA0 + mi * 16, ki * 2 + chA));
#pragma unroll
            for (int p = 0; p < 4; p++) {
                uint32_t bf[4];
                ldsm4(bf, bbase + SA(rB0 + p * 16, ki * 2 + chB));
#pragma unroll
                for (int mi = 0; mi < 2; mi++) {
                    mma_f16(acc[mi][2 * p], af[mi], bf);
                    mma_f16(acc[mi][2 * p + 1], af[mi], bf + 2);
                }
            }
        }
        if (kt == 31) break;
        __syncthreads();
#pragma unroll
        for (int j = 0; j < 4; j++) {
            uint4 av = *(const uint4*)(mp + (kt + 1) * 64 + j * 8);
            STS128V(sb + so[j], av.x, av.y, av.z, av.w);
        }
        if (kt < 30) {
            int s0n = (kt + 2) * 64;
#pragma unroll
            for (int j = 0; j < 4; j++)
                CPASYNC16(sb + 16384u + (uint32_t)(kt & 1) * 16384u + so[j],
                          (const void*)(up + s0n + j * 8));
        }
        CPCOMMIT();
        CPWAIT1();
        __syncthreads();
    }

    int g = lane >> 2, tg = lane & 3;
#pragma unroll
    for (int mi = 0; mi < 2; mi++) {
#pragma unroll
        for (int h = 0; h < 2; h++) {
            int row = warpM * 32 + mi * 16 + h * 8 + g;
            float zi = g_zinv[b * LL + l0 + row];
            float* orow = out + ((size_t)(b * LL + l0 + row)) * DD + d0 + warpN * 64;
#pragma unroll
            for (int ni = 0; ni < 8; ni++) {
                float2 val;
                val.x = acc[mi][ni][h * 2] * zi;
                val.y = acc[mi][ni][h * 2 + 1] * zi;
                *(float2*)(orow + ni * 8 + tg * 2) = val;
            }
        }
    }
}

// ---------------- launch ----------------
extern "C" void kernel_launch(void* const* d_in, const int* in_sizes, int n_in,
                              void* d_out, int out_size) {
    (void)in_sizes; (void)n_in; (void)out_size;
    const float* k = (const float*)d_in[1];
    const float* v = (const float*)d_in[2];
    const void* mask = d_in[3];
    const float* W2 = (const float*)d_in[6];
    const float* b2 = (const float*)d_in[7];

    float* out = (float*)d_out;                // [B, L, D]
    float* attn = out + (size_t)BB * LL * DD;  // [B, L, L]

    detect_kernel<<<1, 1024>>>((const unsigned int*)mask);
    repack_kernel<<<(int)(((size_t)BB * LL * LL) / 4096), 256>>>(mask);
    ks_kernel<<<BB * LL / 8, 256>>>(k, W2, b2);
    maxexp_kernel<<<BB, 256>>>();
    ut_kernel<<<dim3(DD / 32, LL / 32, BB), 256>>>(v);
    zattn_kernel<<<BB * LL / 8, 256>>>(attn);

    dim3 grid(DD / 128, LL / 128, BB);
    cudaError_t e = cudaFuncSetAttribute(gemm_kernel96,
                                         cudaFuncAttributeMaxDynamicSharedMemorySize, 98304);
    if (e == cudaSuccess) {
        gemm_kernel96<<<grid, 256, 98304>>>(out);
    } else {
        (void)cudaGetLastError();
        gemm_kernel48<<<grid, 256>>>(out);
    }
}

// round 9
// speedup vs baseline: 1.1047x; 1.1047x over previous
#include <cuda_runtime.h>
#include <cuda_bf16.h>
#include <cuda_fp16.h>
#include <cstdint>
#include <cstddef>

#define BB 8
#define LL 2048
#define DD 1024

// ---------------- scratch (device globals; allocation-free) ----------------
__device__ float g_ks[BB * LL];
__device__ float g_e[BB * LL];
__device__ float g_zinv[BB * LL];
__device__ int g_is32;
__device__ unsigned char g_mask8[(size_t)BB * LL * LL];  // 0/1 bytes (written by zattn)
__device__ __half g_ut[(size_t)BB * DD * LL];            // U^T fp16: [b][d][s]

// ---------------- helpers ----------------
static __device__ __forceinline__ uint32_t smem_u32(const void* p) {
    uint32_t a;
    asm("{ .reg .u64 t; cvta.to.shared.u64 t, %1; cvt.u32.u64 %0, t; }" : "=r"(a) : "l"(p));
    return a;
}

#define STS128V(a, r0, r1, r2, r3) \
    asm volatile("st.shared.v4.b32 [%0], {%1, %2, %3, %4};" :: "r"(a), "r"(r0), "r"(r1), "r"(r2), "r"(r3) : "memory")

#define CPASYNC16(dst, src) \
    asm volatile("cp.async.cg.shared.global [%0], [%1], 16;" :: "r"(dst), "l"(src) : "memory")
#define CPCOMMIT() asm volatile("cp.async.commit_group;" ::: "memory")
#define CPWAIT1() asm volatile("cp.async.wait_group 1;" ::: "memory")

static __device__ __forceinline__ void ldsm4(uint32_t* r, uint32_t addr) {
    asm volatile("ldmatrix.sync.aligned.m8n8.x4.shared.b16 {%0,%1,%2,%3}, [%4];"
                 : "=r"(r[0]), "=r"(r[1]), "=r"(r[2]), "=r"(r[3]) : "r"(addr));
}

static __device__ __forceinline__ void mma_f16(float* c, const uint32_t* a, const uint32_t* b) {
    asm volatile(
        "mma.sync.aligned.m16n8k16.row.col.f32.f16.f16.f32 "
        "{%0,%1,%2,%3}, {%4,%5,%6,%7}, {%8,%9}, {%0,%1,%2,%3};"
        : "+f"(c[0]), "+f"(c[1]), "+f"(c[2]), "+f"(c[3])
        : "r"(a[0]), "r"(a[1]), "r"(a[2]), "r"(a[3]), "r"(b[0]), "r"(b[1]));
}

// swizzled SMEM offset: tiles are 128 rows x 64 fp16 (128B rows, 8 x 16B chunks)
#define SA(row, chunk) ((uint32_t)((row) * 128 + ((((uint32_t)(chunk)) ^ ((uint32_t)(row) & 7u)) << 4)))

// 2 mask bytes -> fp16x2 (1.0 where NOT masked, 0.0 where masked)
static __device__ __forceinline__ uint32_t m2f16(uint32_t w) {
    uint32_t lo = (w & 0x000000FFu) ? 0u : 0x3C00u;
    uint32_t hi = (w & 0x0000FF00u) ? 0u : 0x3C00u;
    return lo | (hi << 16);
}

// ---------------- Pass 0: detect mask dtype (int32 vs uint8) ----------------
__global__ void detect_kernel(const unsigned int* m) {
    __shared__ int s;
    if (threadIdx.x == 0) s = 0;
    __syncthreads();
    if (m[threadIdx.x] & 0xFFFFFF00u) atomicOr(&s, 1);
    __syncthreads();
    if (threadIdx.x == 0) g_is32 = s ? 0 : 1;
}

// ---------------- Pass 1: k_s[b,s] = k . W2 + b2 ----------------
__global__ __launch_bounds__(256) void ks_kernel(const float* __restrict__ k,
                                                 const float* __restrict__ W2,
                                                 const float* __restrict__ b2) {
    int w = threadIdx.x >> 5, lane = threadIdx.x & 31;
    int r = blockIdx.x * 8 + w;
    const float4* kr = (const float4*)(k + (size_t)r * DD);
    const float4* w4 = (const float4*)W2;
    float s = 0.f;
#pragma unroll
    for (int i = 0; i < 8; i++) {
        float4 a = kr[lane + 32 * i];
        float4 b = w4[lane + 32 * i];
        s += a.x * b.x + a.y * b.y + a.z * b.z + a.w * b.w;
    }
#pragma unroll
    for (int o = 16; o; o >>= 1) s += __shfl_xor_sync(0xFFFFFFFFu, s, o);
    if (lane == 0) g_ks[r] = s + b2[0];
}

// ---------------- Pass 2: per-b max and e = exp(ks - max) ----------------
__global__ __launch_bounds__(256) void maxexp_kernel() {
    int b = blockIdx.x;
    __shared__ float red[256];
    float m = -1e30f;
    for (int i = threadIdx.x; i < LL; i += 256) m = fmaxf(m, g_ks[b * LL + i]);
    red[threadIdx.x] = m;
    __syncthreads();
    for (int s = 128; s; s >>= 1) {
        if (threadIdx.x < s) red[threadIdx.x] = fmaxf(red[threadIdx.x], red[threadIdx.x + s]);
        __syncthreads();
    }
    float M = red[0];
    for (int i = threadIdx.x; i < LL; i += 256) g_e[b * LL + i] = expf(g_ks[b * LL + i] - M);
}

// ---------------- Pass 3: U^T fp16 build (U = e * v, transposed to [b][d][s]) ----------------
__global__ __launch_bounds__(256) void ut_kernel(const float* __restrict__ v) {
    __shared__ float tile[32][33];
    int b = blockIdx.z;
    int s0 = blockIdx.y * 32, d0 = blockIdx.x * 32;
    int r = threadIdx.x >> 5, c = threadIdx.x & 31;
#pragma unroll
    for (int i = 0; i < 4; i++) {
        int sl = r + i * 8;
        tile[sl][c] = g_e[b * LL + s0 + sl] * v[((size_t)b * LL + s0 + sl) * DD + d0 + c];
    }
    __syncthreads();
#pragma unroll
    for (int i = 0; i < 4; i++) {
        int dl = r + i * 8;
        float u = tile[c][dl];
        g_ut[((size_t)b * DD + d0 + dl) * LL + s0 + c] = __float2half(u);
    }
}

// ---------------- Pass 4: fused repack + Z + attn ----------------
// Reads ORIGINAL mask (int32 or uint8 per g_is32); writes g_mask8, g_zinv, attn.
__global__ __launch_bounds__(256) void zattn_kernel(const void* __restrict__ maskp,
                                                    float* __restrict__ attn) {
    __shared__ __align__(16) float se[LL];
    int b = blockIdx.x >> 8;
    int l0 = (blockIdx.x & 255) * 8;
    for (int i = threadIdx.x; i < LL; i += 256) se[i] = g_e[b * LL + i];
    __syncthreads();
    int w = threadIdx.x >> 5, lane = threadIdx.x & 31;
    int l = l0 + w;
    const float4* e4 = (const float4*)se;
    uint32_t mw[16];
    if (g_is32) {
        const uint4* mrow = (const uint4*)((const int*)maskp + (size_t)(b * LL + l) * LL);
#pragma unroll
        for (int i = 0; i < 16; i++) {
            uint4 wv = mrow[lane + 32 * i];
            mw[i] = (wv.x ? 1u : 0u) | (wv.y ? 0x100u : 0u) |
                    (wv.z ? 0x10000u : 0u) | (wv.w ? 0x1000000u : 0u);
        }
    } else {
        const uint32_t* mrow = (const uint32_t*)((const unsigned char*)maskp + (size_t)(b * LL + l) * LL);
#pragma unroll
        for (int i = 0; i < 16; i++) mw[i] = mrow[lane + 32 * i];
    }
    // side-product: normalized byte mask for the GEMM
    uint32_t* m8row = (uint32_t*)(g_mask8 + (size_t)(b * LL + l) * LL);
    float z = 0.f;
#pragma unroll
    for (int i = 0; i < 16; i++) {
        m8row[lane + 32 * i] = mw[i];
        float4 ev = e4[lane + 32 * i];
        if (!(mw[i] & 0x000000FFu)) z += ev.x;
        if (!(mw[i] & 0x0000FF00u)) z += ev.y;
        if (!(mw[i] & 0x00FF0000u)) z += ev.z;
        if (!(mw[i] & 0xFF000000u)) z += ev.w;
    }
#pragma unroll
    for (int o = 16; o; o >>= 1) z += __shfl_xor_sync(0xFFFFFFFFu, z, o);
    float zi = 1.f / z;
    if (lane == 0) g_zinv[b * LL + l] = zi;
    float4* arow = (float4*)(attn + ((size_t)b * LL + l) * LL);
#pragma unroll
    for (int i = 0; i < 16; i++) {
        uint32_t m = mw[i];
        float4 ev = e4[lane + 32 * i];
        float4 o4;
        o4.x = (m & 0x000000FFu) ? 0.f : ev.x * zi;
        o4.y = (m & 0x0000FF00u) ? 0.f : ev.y * zi;
        o4.z = (m & 0x00FF0000u) ? 0.f : ev.z * zi;
        o4.w = (m & 0xFF000000u) ? 0.f : ev.w * zi;
        arow[lane + 32 * i] = o4;
    }
}

// ================= Pass 5 (preferred): 3-stage pipelined fp16 GEMM, 96KB dyn SMEM =================
// CTA tile 128(l) x 128(d), K-chunk 64(s), stage st: [A 16KB | B 16KB].
// Loop: wait -> barrier -> cp.async B(kt+2) -> LDG A(kt+2) -> compute(kt) -> cvt+STS A(kt+2).
__global__ __launch_bounds__(256, 2) void gemm_kernel96(float* __restrict__ out) {
    extern __shared__ __align__(128) unsigned char dsm[];
    uint32_t sb = smem_u32(dsm);
    int tid = threadIdx.x, wid = tid >> 5, lane = tid & 31;
    int b = blockIdx.z, l0 = blockIdx.y * 128, d0 = blockIdx.x * 128;
    int warpM = wid & 3, warpN = wid >> 2;

    float acc[2][8][4];
#pragma unroll
    for (int i = 0; i < 2; i++)
#pragma unroll
        for (int j = 0; j < 8; j++)
#pragma unroll
            for (int q = 0; q < 4; q++) acc[i][j][q] = 0.f;

    int sub = lane >> 3, l7 = lane & 7;
    int rA0 = warpM * 32 + (sub & 1) * 8 + l7;
    int chA = (sub >> 1);
    int rB0 = warpN * 64 + (sub >> 1) * 8 + l7;
    int chB = (sub & 1);

    int srow = tid >> 1;
    int sc4 = (tid & 1) * 4;
    const unsigned char* mp = g_mask8 + ((size_t)(b * LL + l0 + srow)) * LL + sc4 * 8;
    const __half* up = g_ut + ((size_t)(b * DD + d0 + srow)) * LL + sc4 * 8;
    uint32_t so[4];
#pragma unroll
    for (int j = 0; j < 4; j++) so[j] = SA(srow, sc4 + j);

    // ---- prologue: stages 0 and 1 ----
#pragma unroll
    for (int st = 0; st < 2; st++) {
        uint32_t ab = sb + (uint32_t)st * 32768u;
        uint4 q0 = *(const uint4*)(mp + st * 64);
        uint4 q1 = *(const uint4*)(mp + st * 64 + 16);
        STS128V(ab + so[0], m2f16(q0.x), m2f16(q0.x >> 16), m2f16(q0.y), m2f16(q0.y >> 16));
        STS128V(ab + so[1], m2f16(q0.z), m2f16(q0.z >> 16), m2f16(q0.w), m2f16(q0.w >> 16));
        STS128V(ab + so[2], m2f16(q1.x), m2f16(q1.x >> 16), m2f16(q1.y), m2f16(q1.y >> 16));
        STS128V(ab + so[3], m2f16(q1.z), m2f16(q1.z >> 16), m2f16(q1.w), m2f16(q1.w >> 16));
#pragma unroll
        for (int j = 0; j < 4; j++)
            CPASYNC16(ab + 16384u + so[j], (const void*)(up + st * 64 + j * 8));
        CPCOMMIT();
    }

    int st = 0;  // kt % 3
    for (int kt = 0; kt < 32; ++kt) {
        CPWAIT1();       // B(kt) arrived (only B(kt+1) pending)
        __syncthreads(); // compute(kt-1) done everywhere; stage (kt+2)%3 free; stage kt visible

        int stn = st + 2; if (stn >= 3) stn -= 3;
        uint32_t nb = sb + (uint32_t)stn * 32768u;

        // ---- cp.async B(kt+2) first (pure DMA, overlaps compute) ----
        if (kt < 30) {
            int s0n = (kt + 2) * 64;
#pragma unroll
            for (int j = 0; j < 4; j++)
                CPASYNC16(nb + 16384u + so[j], (const void*)(up + s0n + j * 8));
        }
        CPCOMMIT();

        // ---- LDG A(kt+2) into regs (latency covered by compute) ----
        uint4 q0, q1;
        if (kt < 30) {
            int s0n = (kt + 2) * 64;
            q0 = *(const uint4*)(mp + s0n);
            q1 = *(const uint4*)(mp + s0n + 16);
        }

        // ---- compute chunk kt from stage st ----
        uint32_t abase = sb + (uint32_t)st * 32768u;
        uint32_t bbase = abase + 16384u;
#pragma unroll
        for (int ki = 0; ki < 4; ki++) {
            uint32_t af[2][4];
#pragma unroll
            for (int mi = 0; mi < 2; mi++)
                ldsm4(af[mi], abase + SA(rA0 + mi * 16, ki * 2 + chA));
#pragma unroll
            for (int p = 0; p < 4; p++) {
                uint32_t bf[4];
                ldsm4(bf, bbase + SA(rB0 + p * 16, ki * 2 + chB));
#pragma unroll
                for (int mi = 0; mi < 2; mi++) {
                    mma_f16(acc[mi][2 * p], af[mi], bf);
                    mma_f16(acc[mi][2 * p + 1], af[mi], bf + 2);
                }
            }
        }

        // ---- convert + STS A(kt+2) ----
        if (kt < 30) {
            STS128V(nb + so[0], m2f16(q0.x), m2f16(q0.x >> 16), m2f16(q0.y), m2f16(q0.y >> 16));
            STS128V(nb + so[1], m2f16(q0.z), m2f16(q0.z >> 16), m2f16(q0.w), m2f16(q0.w >> 16));
            STS128V(nb + so[2], m2f16(q1.x), m2f16(q1.x >> 16), m2f16(q1.y), m2f16(q1.y >> 16));
            STS128V(nb + so[3], m2f16(q1.z), m2f16(q1.z >> 16), m2f16(q1.w), m2f16(q1.w >> 16));
        }
        if (++st == 3) st = 0;
    }

    // epilogue
    int g = lane >> 2, tg = lane & 3;
#pragma unroll
    for (int mi = 0; mi < 2; mi++) {
#pragma unroll
        for (int h = 0; h < 2; h++) {
            int row = warpM * 32 + mi * 16 + h * 8 + g;
            float zi = g_zinv[b * LL + l0 + row];
            float* orow = out + ((size_t)(b * LL + l0 + row)) * DD + d0 + warpN * 64;
#pragma unroll
            for (int ni = 0; ni < 8; ni++) {
                float2 val;
                val.x = acc[mi][ni][h * 2] * zi;
                val.y = acc[mi][ni][h * 2 + 1] * zi;
                *(float2*)(orow + ni * 8 + tg * 2) = val;
            }
        }
    }
}

// ================= Pass 5 (fallback): 48KB static, 2-stage B, byte A =================
__global__ __launch_bounds__(256, 2) void gemm_kernel48(float* __restrict__ out) {
    __shared__ __align__(128) unsigned char smem[49152];
    uint32_t sb = smem_u32(smem);
    int tid = threadIdx.x, wid = tid >> 5, lane = tid & 31;
    int b = blockIdx.z, l0 = blockIdx.y * 128, d0 = blockIdx.x * 128;
    int warpM = wid & 3, warpN = wid >> 2;

    float acc[2][8][4];
#pragma unroll
    for (int i = 0; i < 2; i++)
#pragma unroll
        for (int j = 0; j < 8; j++)
#pragma unroll
            for (int q = 0; q < 4; q++) acc[i][j][q] = 0.f;

    int sub = lane >> 3, l7 = lane & 7;
    int rA0 = warpM * 32 + (sub & 1) * 8 + l7;
    int chA = (sub >> 1);
    int rB0 = warpN * 64 + (sub >> 1) * 8 + l7;
    int chB = (sub & 1);

    int srow = tid >> 1;
    int sc4 = (tid & 1) * 4;
    const unsigned char* mp = g_mask8 + ((size_t)(b * LL + l0 + srow)) * LL + sc4 * 8;
    const __half* up = g_ut + ((size_t)(b * DD + d0 + srow)) * LL + sc4 * 8;
    uint32_t so[4];
#pragma unroll
    for (int j = 0; j < 4; j++) so[j] = SA(srow, sc4 + j);

    uint4 q0 = *(const uint4*)(mp + 0);
    uint4 q1 = *(const uint4*)(mp + 16);
#pragma unroll
    for (int j = 0; j < 4; j++)
        CPASYNC16(sb + 16384u + so[j], (const void*)(up + 0 + j * 8));
    CPCOMMIT();
#pragma unroll
    for (int j = 0; j < 4; j++)
        CPASYNC16(sb + 32768u + so[j], (const void*)(up + 64 + j * 8));
    CPCOMMIT();
    STS128V(sb + so[0], m2f16(q0.x), m2f16(q0.x >> 16), m2f16(q0.y), m2f16(q0.y >> 16));
    STS128V(sb + so[1], m2f16(q0.z), m2f16(q0.z >> 16), m2f16(q0.w), m2f16(q0.w >> 16));
    STS128V(sb + so[2], m2f16(q1.x), m2f16(q1.x >> 16), m2f16(q1.y), m2f16(q1.y >> 16));
    STS128V(sb + so[3], m2f16(q1.z), m2f16(q1.z >> 16), m2f16(q1.w), m2f16(q1.w >> 16));
    q0 = *(const uint4*)(mp + 64);
    q1 = *(const uint4*)(mp + 80);
    CPWAIT1();
    __syncthreads();

    for (int kt = 0; kt < 32; ++kt) {
        uint32_t bbase = sb + 16384u + (uint32_t)(kt & 1) * 16384u;
#pragma unroll
        for (int ki = 0; ki < 4; ki++) {
            uint32_t af[2][4];
#pragma unroll
            for (int mi = 0; mi < 2; mi++)
                ldsm4(af[mi], sb + SA(rA0 + mi * 16, ki * 2 + chA));
#pragma unroll
            for (int p = 0; p < 4; p++) {
                uint32_t bf[4];
                ldsm4(bf, bbase + SA(rB0 + p * 16, ki * 2 + chB));
#pragma unroll
                for (int mi = 0; mi < 2; mi++) {
                    mma_f16(acc[mi][2 * p], af[mi], bf);
                    mma_f16(acc[mi][2 * p + 1], af[mi], bf + 2);
                }
            }
        }
        if (kt == 31) break;
        __syncthreads();
        STS128V(sb + so[0], m2f16(q0.x), m2f16(q0.x >> 16), m2f16(q0.y), m2f16(q0.y >> 16));
        STS128V(sb + so[1], m2f16(q0.z), m2f16(q0.z >> 16), m2f16(q0.w), m2f16(q0.w >> 16));
        STS128V(sb + so[2], m2f16(q1.x), m2f16(q1.x >> 16), m2f16(q1.y), m2f16(q1.y >> 16));
        STS128V(sb + so[3], m2f16(q1.z), m2f16(q1.z >> 16), m2f16(q1.w), m2f16(q1.w >> 16));
        if (kt < 30) {
            int s0n = (kt + 2) * 64;
            q0 = *(const uint4*)(mp + s0n);
            q1 = *(const uint4*)(mp + s0n + 16);
#pragma unroll
            for (int j = 0; j < 4; j++)
                CPASYNC16(sb + 16384u + (uint32_t)(kt & 1) * 16384u + so[j],
                          (const void*)(up + s0n + j * 8));
        }
        CPCOMMIT();
        CPWAIT1();
        __syncthreads();
    }

    int g = lane >> 2, tg = lane & 3;
#pragma unroll
    for (int mi = 0; mi < 2; mi++) {
#pragma unroll
        for (int h = 0; h < 2; h++) {
            int row = warpM * 32 + mi * 16 + h * 8 + g;
            float zi = g_zinv[b * LL + l0 + row];
            float* orow = out + ((size_t)(b * LL + l0 + row)) * DD + d0 + warpN * 64;
#pragma unroll
            for (int ni = 0; ni < 8; ni++) {
                float2 val;
                val.x = acc[mi][ni][h * 2] * zi;
                val.y = acc[mi][ni][h * 2 + 1] * zi;
                *(float2*)(orow + ni * 8 + tg * 2) = val;
            }
        }
    }
}

// ---------------- launch ----------------
extern "C" void kernel_launch(void* const* d_in, const int* in_sizes, int n_in,
                              void* d_out, int out_size) {
    (void)in_sizes; (void)n_in; (void)out_size;
    const float* k = (const float*)d_in[1];
    const float* v = (const float*)d_in[2];
    const void* mask = d_in[3];
    const float* W2 = (const float*)d_in[6];
    const float* b2 = (const float*)d_in[7];

    float* out = (float*)d_out;                // [B, L, D]
    float* attn = out + (size_t)BB * LL * DD;  // [B, L, L]

    detect_kernel<<<1, 1024>>>((const unsigned int*)mask);
    ks_kernel<<<BB * LL / 8, 256>>>(k, W2, b2);
    maxexp_kernel<<<BB, 256>>>();
    ut_kernel<<<dim3(DD / 32, LL / 32, BB), 256>>>(v);
    zattn_kernel<<<BB * LL / 8, 256>>>(mask, attn);

    dim3 grid(DD / 128, LL / 128, BB);
    cudaError_t e = cudaFuncSetAttribute(gemm_kernel96,
                                         cudaFuncAttributeMaxDynamicSharedMemorySize, 98304);
    if (e == cudaSuccess) {
        gemm_kernel96<<<grid, 256, 98304>>>(out);
    } else {
        (void)cudaGetLastError();
        gemm_kernel48<<<grid, 256>>>(out);
    }
}